// round 2
// baseline (speedup 1.0000x reference)
#include <cuda_runtime.h>
#include <math.h>

#define D    128
#define DOUT 40
#define NMAX 100000
#define EMAX 1600000

static inline int cdiv(int a, int b) { return (a + b - 1) / b; }

// ---------------- scratch (static device globals; no allocation) ----------------
__device__ __align__(16) float g_xw  [(size_t)NMAX * D];
__device__ __align__(16) float g_h   [(size_t)NMAX * D];
__device__ __align__(16) float g_agg [(size_t)NMAX * D];
__device__ __align__(16) float g_xw2 [(size_t)NMAX * DOUT];
__device__ __align__(16) float g_agg2[(size_t)NMAX * DOUT];
__device__ float g_norm[EMAX];
__device__ float g_deg [NMAX];
__device__ float g_dinv[NMAX];
__device__ int   g_idx [2 * EMAX];   // converted int32 src|dst
__device__ int   g_is64;
__device__ __align__(16) float g_bnsum  [D];
__device__ __align__(16) float g_bnsumsq[D];
__device__ __align__(16) float g_scale  [D];
__device__ __align__(16) float g_shift  [D];

// ---------------- index dtype detect + convert ----------------
// int64 little-endian with values < 2^31: every odd 32-bit word is 0.
__global__ void detect_kernel(const unsigned* __restrict__ w, int twoE) {
    if (threadIdx.x == 0 && blockIdx.x == 0) {
        int nchk = twoE < 256 ? twoE : 256;
        int is64 = 1;
        for (int i = 0; i < nchk; i++)
            if (w[2 * i + 1] != 0u) { is64 = 0; break; }
        g_is64 = is64;
    }
}

__global__ void convert_kernel(const void* __restrict__ ei, int twoE) {
    int i = blockIdx.x * blockDim.x + threadIdx.x;
    if (i < twoE) {
        int v;
        if (g_is64) v = (int)((const long long*)ei)[i];
        else        v = ((const int*)ei)[i];
        g_idx[i] = v;
    }
}

// ---------------- degree / norm precompute ----------------
__global__ void deg_kernel(const float* __restrict__ ew, int E) {
    int e = blockIdx.x * blockDim.x + threadIdx.x;
    if (e < E) atomicAdd(&g_deg[g_idx[E + e]], ew[e]);
}

__global__ void dinv_kernel(int n) {
    int i = blockIdx.x * blockDim.x + threadIdx.x;
    if (i < n) g_dinv[i] = rsqrtf(g_deg[i] + 1.0f);
}

__global__ void norm_kernel(const float* __restrict__ ew, int E) {
    int e = blockIdx.x * blockDim.x + threadIdx.x;
    if (e < E)
        g_norm[e] = g_dinv[g_idx[e]] * ew[e] * g_dinv[g_idx[E + e]];
}

// ---------------- fused BN+ReLU on load ----------------
__device__ __forceinline__ float4 bnrelu4(float4 v, int c4) {
    float4 sc = ((const float4*)g_scale)[c4];
    float4 sh = ((const float4*)g_shift)[c4];
    v.x = fmaxf(fmaf(v.x, sc.x, sh.x), 0.0f);
    v.y = fmaxf(fmaf(v.y, sc.y, sh.y), 0.0f);
    v.z = fmaxf(fmaf(v.z, sc.z, sh.z), 0.0f);
    v.w = fmaxf(fmaf(v.w, sc.w, sh.w), 0.0f);
    return v;
}

// ---------------- GEMM: C[n,128] = act(A[n,128]) @ W[128,128] ----------------
// Block: 256 threads, 64 rows x 128 cols per block. W fully SMEM-resident.
#define GEMM_SMEM ((128 * 128 + 64 * 132) * 4)

template <bool FUSE_BN>
__global__ void gemm128(const float* __restrict__ A, const float* __restrict__ W,
                        float* __restrict__ C, int n) {
    extern __shared__ float smem[];
    float* sW = smem;                 // [128][128]
    float* sX = smem + 128 * 128;     // [64][132] padded

    int tid = threadIdx.x;
    int row0 = blockIdx.x * 64;

    // load W (4096 float4)
    const float4* W4  = (const float4*)W;
    float4*       sW4 = (float4*)sW;
    #pragma unroll
    for (int i = tid; i < 4096; i += 256) sW4[i] = W4[i];

    // load A tile (2048 float4) with optional fused BN+ReLU
    const float4* A4  = (const float4*)A + (size_t)row0 * 32;
    float4*       sX4 = (float4*)sX;
    #pragma unroll
    for (int i = tid; i < 2048; i += 256) {
        int r = i >> 5, c4 = i & 31;
        float4 v = make_float4(0.f, 0.f, 0.f, 0.f);
        if (row0 + r < n) v = A4[i];
        if (FUSE_BN) v = bnrelu4(v, c4);
        sX4[r * 33 + c4] = v;
    }
    __syncthreads();

    int tx = tid & 15, ty = tid >> 4;   // cols = tx*8 + j ; rows = ty*4 + i
    float acc[4][8];
    #pragma unroll
    for (int i = 0; i < 4; i++)
        #pragma unroll
        for (int j = 0; j < 8; j++) acc[i][j] = 0.f;

    const float4* sWr = (const float4*)sW;
    #pragma unroll 4
    for (int k = 0; k < 128; k++) {
        float4 w0 = sWr[k * 32 + tx * 2];
        float4 w1 = sWr[k * 32 + tx * 2 + 1];
        float xv[4];
        #pragma unroll
        for (int i = 0; i < 4; i++) xv[i] = sX[(ty * 4 + i) * 132 + k];
        #pragma unroll
        for (int i = 0; i < 4; i++) {
            acc[i][0] = fmaf(xv[i], w0.x, acc[i][0]);
            acc[i][1] = fmaf(xv[i], w0.y, acc[i][1]);
            acc[i][2] = fmaf(xv[i], w0.z, acc[i][2]);
            acc[i][3] = fmaf(xv[i], w0.w, acc[i][3]);
            acc[i][4] = fmaf(xv[i], w1.x, acc[i][4]);
            acc[i][5] = fmaf(xv[i], w1.y, acc[i][5]);
            acc[i][6] = fmaf(xv[i], w1.z, acc[i][6]);
            acc[i][7] = fmaf(xv[i], w1.w, acc[i][7]);
        }
    }

    #pragma unroll
    for (int i = 0; i < 4; i++) {
        int r = row0 + ty * 4 + i;
        if (r < n) {
            float4* Cr = (float4*)(C + (size_t)r * 128);
            Cr[tx * 2]     = make_float4(acc[i][0], acc[i][1], acc[i][2], acc[i][3]);
            Cr[tx * 2 + 1] = make_float4(acc[i][4], acc[i][5], acc[i][6], acc[i][7]);
        }
    }
}

// ---------------- GEMM: C[n,40] = bnrelu(A[n,128]) @ W[128,40] ----------------
__global__ void gemm40(const float* __restrict__ A, const float* __restrict__ W,
                       float* __restrict__ C, int n) {
    __shared__ float sW[128 * 40];   // 20 KB
    __shared__ float sX[32 * 132];   // padded

    int tid = threadIdx.x;
    int row0 = blockIdx.x * 32;

    const float4* W4  = (const float4*)W;
    float4*       sW4 = (float4*)sW;
    #pragma unroll
    for (int i = tid; i < 1280; i += 256) sW4[i] = W4[i];

    const float4* A4  = (const float4*)A + (size_t)row0 * 32;
    float4*       sX4 = (float4*)sX;
    #pragma unroll
    for (int i = tid; i < 1024; i += 256) {
        int r = i >> 5, c4 = i & 31;
        float4 v = make_float4(0.f, 0.f, 0.f, 0.f);
        if (row0 + r < n) v = A4[i];
        v = bnrelu4(v, c4);
        sX4[r * 33 + c4] = v;
    }
    __syncthreads();

    int tx = tid & 7, rt = tid >> 3;   // cols = tx*5 + j (0..39), one row per thread
    float acc[5] = {0.f, 0.f, 0.f, 0.f, 0.f};
    #pragma unroll 4
    for (int k = 0; k < 128; k++) {
        float xv = sX[rt * 132 + k];
        #pragma unroll
        for (int j = 0; j < 5; j++)
            acc[j] = fmaf(xv, sW[k * 40 + tx * 5 + j], acc[j]);
    }
    int row = row0 + rt;
    if (row < n) {
        #pragma unroll
        for (int j = 0; j < 5; j++)
            C[(size_t)row * 40 + tx * 5 + j] = acc[j];
    }
}

// ---------------- edge scatter (D=128): one warp per edge ----------------
__global__ void scatter128(const float* __restrict__ xw, int E) {
    int lane   = threadIdx.x & 31;
    int warp   = (blockIdx.x * blockDim.x + threadIdx.x) >> 5;
    int nwarps = (gridDim.x * blockDim.x) >> 5;
    for (int e = warp; e < E; e += nwarps) {
        int s = __ldg(&g_idx[e]);
        int d = __ldg(&g_idx[E + e]);
        float w = g_norm[e];
        const float4* xr = (const float4*)(xw + (size_t)s * D);
        float4 v = xr[lane];
        float4* ar = ((float4*)(g_agg + (size_t)d * D)) + lane;
        asm volatile("red.global.add.v4.f32 [%0], {%1,%2,%3,%4};"
                     :: "l"(ar), "f"(v.x * w), "f"(v.y * w), "f"(v.z * w), "f"(v.w * w)
                     : "memory");
    }
}

// ---------------- edge scatter (D=40): 16 lanes per edge (10 active) ----------
__global__ void scatter40(int E) {
    int g    = blockIdx.x * blockDim.x + threadIdx.x;
    int l    = g & 15;
    int grp  = g >> 4;
    int ngrp = (gridDim.x * blockDim.x) >> 4;
    if (l >= 10) return;
    for (int e = grp; e < E; e += ngrp) {
        int s = __ldg(&g_idx[e]);
        int d = __ldg(&g_idx[E + e]);
        float w = g_norm[e];
        const float4* xr = (const float4*)(g_xw2 + (size_t)s * DOUT);
        float4 v = xr[l];
        float4* ar = ((float4*)(g_agg2 + (size_t)d * DOUT)) + l;
        asm volatile("red.global.add.v4.f32 [%0], {%1,%2,%3,%4};"
                     :: "l"(ar), "f"(v.x * w), "f"(v.y * w), "f"(v.z * w), "f"(v.w * w)
                     : "memory");
    }
}

// ---------------- self-loop + bias + BN stats ----------------
__global__ void post_bn(const float* __restrict__ agg, const float* __restrict__ xw,
                        const float* __restrict__ b, float* __restrict__ h, int n) {
    int c   = threadIdx.x & 127;
    int sub = threadIdx.x >> 7;      // 0..3
    int r0  = blockIdx.x * 128;
    float bias = b[c];
    float s = 0.f, ss = 0.f;
    for (int i = sub; i < 128; i += 4) {
        int r = r0 + i;
        if (r >= n) break;
        float di = g_dinv[r];
        size_t off = (size_t)r * 128 + c;
        float v = agg[off] + xw[off] * (di * di) + bias;
        h[off] = v;
        s += v;
        ss += v * v;
    }
    atomicAdd(&g_bnsum[c], s);
    atomicAdd(&g_bnsumsq[c], ss);
}

__global__ void bn_final(const float* __restrict__ g, const float* __restrict__ be,
                         float fn) {
    int c = threadIdx.x;
    float mean = g_bnsum[c] / fn;
    float var  = g_bnsumsq[c] / fn - mean * mean;
    float sc   = g[c] * rsqrtf(var + 1e-5f);
    g_scale[c] = sc;
    g_shift[c] = be[c] - mean * sc;
}

// ---------------- final: self-loop + bias + log_softmax ----------------
__global__ void final_kernel(const float* __restrict__ b2, float* __restrict__ out, int n) {
    int w    = (blockIdx.x * blockDim.x + threadIdx.x) >> 5;
    int lane = threadIdx.x & 31;
    if (w >= n) return;
    size_t base = (size_t)w * DOUT;
    float di  = g_dinv[w];
    float di2 = di * di;
    float v0 = g_agg2[base + lane] + g_xw2[base + lane] * di2 + b2[lane];
    float v1 = -1e30f;
    if (lane < 8)
        v1 = g_agg2[base + 32 + lane] + g_xw2[base + 32 + lane] * di2 + b2[32 + lane];
    float m = fmaxf(v0, v1);
    #pragma unroll
    for (int o = 16; o; o >>= 1) m = fmaxf(m, __shfl_xor_sync(0xffffffffu, m, o));
    float s = expf(v0 - m) + (lane < 8 ? expf(v1 - m) : 0.f);
    #pragma unroll
    for (int o = 16; o; o >>= 1) s += __shfl_xor_sync(0xffffffffu, s, o);
    float lse = m + logf(s);
    out[base + lane] = v0 - lse;
    if (lane < 8) out[base + 32 + lane] = v1 - lse;
}

// ---------------- launch ----------------
extern "C" void kernel_launch(void* const* d_in, const int* in_sizes, int n_in,
                              void* d_out, int out_size) {
    const float* x   = (const float*)d_in[0];
    const void*  ei  = d_in[1];
    const float* ew  = (const float*)d_in[2];
    const float* W0  = (const float*)d_in[3];
    const float* b0  = (const float*)d_in[4];
    const float* g0  = (const float*)d_in[5];
    const float* be0 = (const float*)d_in[6];
    const float* W1  = (const float*)d_in[7];
    const float* b1  = (const float*)d_in[8];
    const float* g1  = (const float*)d_in[9];
    const float* be1 = (const float*)d_in[10];
    const float* W2  = (const float*)d_in[11];
    const float* b2  = (const float*)d_in[12];

    int n = in_sizes[0] / D;
    int E = in_sizes[2];
    int twoE = 2 * E;

    cudaFuncSetAttribute(gemm128<false>, cudaFuncAttributeMaxDynamicSharedMemorySize, GEMM_SMEM);
    cudaFuncSetAttribute(gemm128<true>,  cudaFuncAttributeMaxDynamicSharedMemorySize, GEMM_SMEM);

    void *p_deg, *p_agg, *p_agg2, *p_bns, *p_bnss, *p_xw, *p_h, *p_xw2;
    cudaGetSymbolAddress(&p_deg,  g_deg);
    cudaGetSymbolAddress(&p_agg,  g_agg);
    cudaGetSymbolAddress(&p_agg2, g_agg2);
    cudaGetSymbolAddress(&p_bns,  g_bnsum);
    cudaGetSymbolAddress(&p_bnss, g_bnsumsq);
    cudaGetSymbolAddress(&p_xw,   g_xw);
    cudaGetSymbolAddress(&p_h,    g_h);
    cudaGetSymbolAddress(&p_xw2,  g_xw2);
    float* xw  = (float*)p_xw;
    float* h   = (float*)p_h;
    float* agg = (float*)p_agg;
    float* xw2 = (float*)p_xw2;

    const int T = 256;
    int scatter_blocks   = 50000;  // grid-stride: 400k warps over 1.6M edges
    int scatter40_blocks = 25000;

    // index dtype detect + convert to int32
    detect_kernel<<<1, 32>>>((const unsigned*)ei, twoE);
    convert_kernel<<<cdiv(twoE, T), T>>>(ei, twoE);

    // degree / norm precompute (shared across layers)
    cudaMemsetAsync(p_deg, 0, (size_t)n * sizeof(float), 0);
    deg_kernel<<<cdiv(E, T), T>>>(ew, E);
    dinv_kernel<<<cdiv(n, T), T>>>(n);
    norm_kernel<<<cdiv(E, T), T>>>(ew, E);

    // ---- layer 0 ----
    gemm128<false><<<cdiv(n, 64), T, GEMM_SMEM>>>(x, W0, xw, n);
    cudaMemsetAsync(p_agg, 0, (size_t)n * D * sizeof(float), 0);
    scatter128<<<scatter_blocks, T>>>(xw, E);
    cudaMemsetAsync(p_bns, 0, D * sizeof(float), 0);
    cudaMemsetAsync(p_bnss, 0, D * sizeof(float), 0);
    post_bn<<<cdiv(n, 128), 512>>>(agg, xw, b0, h, n);
    bn_final<<<1, D>>>(g0, be0, (float)n);

    // ---- layer 1 ----
    gemm128<true><<<cdiv(n, 64), T, GEMM_SMEM>>>(h, W1, xw, n);
    cudaMemsetAsync(p_agg, 0, (size_t)n * D * sizeof(float), 0);
    scatter128<<<scatter_blocks, T>>>(xw, E);
    cudaMemsetAsync(p_bns, 0, D * sizeof(float), 0);
    cudaMemsetAsync(p_bnss, 0, D * sizeof(float), 0);
    post_bn<<<cdiv(n, 128), 512>>>(agg, xw, b1, h, n);
    bn_final<<<1, D>>>(g1, be1, (float)n);

    // ---- layer 2 + log_softmax ----
    gemm40<<<cdiv(n, 32), T>>>(h, W2, xw2, n);
    cudaMemsetAsync(p_agg2, 0, (size_t)n * DOUT * sizeof(float), 0);
    scatter40<<<scatter40_blocks, T>>>(E);
    final_kernel<<<cdiv(n, 8), T>>>(b2, (float*)d_out, n);
}

// round 3
// speedup vs baseline: 1.3524x; 1.3524x over previous
#include <cuda_runtime.h>
#include <math.h>

#define D    128
#define DOUT 40
#define NMAX 100000
#define EMAX 1600000

static inline int cdiv(int a, int b) { return (a + b - 1) / b; }

// ---------------- scratch (static device globals; no allocation) ----------------
__device__ __align__(16) float g_xw  [(size_t)NMAX * D];
__device__ __align__(16) float g_h   [(size_t)NMAX * D];
__device__ __align__(16) float g_xw2 [(size_t)NMAX * DOUT];
__device__ float g_deg [NMAX];
__device__ float g_dinv[NMAX];
__device__ int   g_idx [2 * EMAX];     // converted int32 src|dst
__device__ int   g_is64;
// CSR
__device__ int   g_cnt [NMAX];
__device__ int   g_rowptr[NMAX + 1];
__device__ int   g_fill[NMAX];
__device__ int   g_bsum[256];
__device__ int   g_boff[256];
__device__ int   g_esrc [EMAX];
__device__ float g_enorm[EMAX];
// BN
__device__ __align__(16) float g_bnsum  [D];
__device__ __align__(16) float g_bnsumsq[D];
__device__ __align__(16) float g_scale  [D];
__device__ __align__(16) float g_shift  [D];

// ---------------- index dtype detect + convert ----------------
__global__ void detect_kernel(const unsigned* __restrict__ w, int twoE) {
    if (threadIdx.x == 0 && blockIdx.x == 0) {
        int nchk = twoE < 256 ? twoE : 256;
        int is64 = 1;
        for (int i = 0; i < nchk; i++)
            if (w[2 * i + 1] != 0u) { is64 = 0; break; }
        g_is64 = is64;
    }
}

__global__ void convert_kernel(const void* __restrict__ ei, int twoE) {
    int i = blockIdx.x * blockDim.x + threadIdx.x;
    if (i < twoE) {
        int v;
        if (g_is64) v = (int)((const long long*)ei)[i];
        else        v = ((const int*)ei)[i];
        g_idx[i] = v;
    }
}

// ---------------- degree (weighted) + dst histogram ----------------
__global__ void degcnt_kernel(const float* __restrict__ ew, int E) {
    int e = blockIdx.x * blockDim.x + threadIdx.x;
    if (e < E) {
        int d = g_idx[E + e];
        atomicAdd(&g_deg[d], ew[e]);
        atomicAdd(&g_cnt[d], 1);
    }
}

__global__ void dinv_kernel(int n) {
    int i = blockIdx.x * blockDim.x + threadIdx.x;
    if (i < n) g_dinv[i] = rsqrtf(g_deg[i] + 1.0f);
}

// ---------------- exclusive scan of g_cnt -> g_rowptr (3-pass) ----------------
__global__ void scan1(int n) {
    __shared__ int sm[512];
    int i = blockIdx.x * 512 + threadIdx.x;
    int v = (i < n) ? g_cnt[i] : 0;
    sm[threadIdx.x] = v;
    __syncthreads();
    #pragma unroll
    for (int o = 1; o < 512; o <<= 1) {
        int t = (threadIdx.x >= o) ? sm[threadIdx.x - o] : 0;
        __syncthreads();
        sm[threadIdx.x] += t;
        __syncthreads();
    }
    if (i < n) g_rowptr[i] = sm[threadIdx.x] - v;   // exclusive within block
    if (threadIdx.x == 511) g_bsum[blockIdx.x] = sm[511];
}

__global__ void scan2(int nb) {
    __shared__ int sm[256];
    int v = (threadIdx.x < nb) ? g_bsum[threadIdx.x] : 0;
    sm[threadIdx.x] = v;
    __syncthreads();
    #pragma unroll
    for (int o = 1; o < 256; o <<= 1) {
        int t = (threadIdx.x >= o) ? sm[threadIdx.x - o] : 0;
        __syncthreads();
        sm[threadIdx.x] += t;
        __syncthreads();
    }
    if (threadIdx.x < nb) g_boff[threadIdx.x] = sm[threadIdx.x] - v;
}

__global__ void scan3(int n, int E) {
    int i = blockIdx.x * blockDim.x + threadIdx.x;
    if (i < n) g_rowptr[i] += g_boff[i >> 9];
    if (i == 0) g_rowptr[n] = E;
}

// ---------------- CSR fill (also computes per-edge norm) ----------------
__global__ void fill_kernel(const float* __restrict__ ew, int E) {
    int e = blockIdx.x * blockDim.x + threadIdx.x;
    if (e < E) {
        int s = g_idx[e];
        int d = g_idx[E + e];
        int pos = g_rowptr[d] + atomicAdd(&g_fill[d], 1);
        g_esrc[pos]  = s;
        g_enorm[pos] = g_dinv[s] * ew[e] * g_dinv[d];
    }
}

// ---------------- fused BN+ReLU on load ----------------
__device__ __forceinline__ float4 bnrelu4(float4 v, int c4) {
    float4 sc = ((const float4*)g_scale)[c4];
    float4 sh = ((const float4*)g_shift)[c4];
    v.x = fmaxf(fmaf(v.x, sc.x, sh.x), 0.0f);
    v.y = fmaxf(fmaf(v.y, sc.y, sh.y), 0.0f);
    v.z = fmaxf(fmaf(v.z, sc.z, sh.z), 0.0f);
    v.w = fmaxf(fmaf(v.w, sc.w, sh.w), 0.0f);
    return v;
}

// ---------------- GEMM: C[n,128] = act(A[n,128]) @ W[128,128] ----------------
#define GEMM_SMEM ((128 * 128 + 64 * 132) * 4)

template <bool FUSE_BN>
__global__ void gemm128(const float* __restrict__ A, const float* __restrict__ W,
                        float* __restrict__ C, int n) {
    extern __shared__ float smem[];
    float* sW = smem;                 // [128][128]
    float* sX = smem + 128 * 128;     // [64][132] padded

    int tid = threadIdx.x;
    int row0 = blockIdx.x * 64;

    const float4* W4  = (const float4*)W;
    float4*       sW4 = (float4*)sW;
    #pragma unroll
    for (int i = tid; i < 4096; i += 256) sW4[i] = W4[i];

    const float4* A4  = (const float4*)A + (size_t)row0 * 32;
    float4*       sX4 = (float4*)sX;
    #pragma unroll
    for (int i = tid; i < 2048; i += 256) {
        int r = i >> 5, c4 = i & 31;
        float4 v = make_float4(0.f, 0.f, 0.f, 0.f);
        if (row0 + r < n) v = A4[i];
        if (FUSE_BN) v = bnrelu4(v, c4);
        sX4[r * 33 + c4] = v;
    }
    __syncthreads();

    int tx = tid & 15, ty = tid >> 4;
    float acc[4][8];
    #pragma unroll
    for (int i = 0; i < 4; i++)
        #pragma unroll
        for (int j = 0; j < 8; j++) acc[i][j] = 0.f;

    const float4* sWr = (const float4*)sW;
    #pragma unroll 4
    for (int k = 0; k < 128; k++) {
        float4 w0 = sWr[k * 32 + tx * 2];
        float4 w1 = sWr[k * 32 + tx * 2 + 1];
        float xv[4];
        #pragma unroll
        for (int i = 0; i < 4; i++) xv[i] = sX[(ty * 4 + i) * 132 + k];
        #pragma unroll
        for (int i = 0; i < 4; i++) {
            acc[i][0] = fmaf(xv[i], w0.x, acc[i][0]);
            acc[i][1] = fmaf(xv[i], w0.y, acc[i][1]);
            acc[i][2] = fmaf(xv[i], w0.z, acc[i][2]);
            acc[i][3] = fmaf(xv[i], w0.w, acc[i][3]);
            acc[i][4] = fmaf(xv[i], w1.x, acc[i][4]);
            acc[i][5] = fmaf(xv[i], w1.y, acc[i][5]);
            acc[i][6] = fmaf(xv[i], w1.z, acc[i][6]);
            acc[i][7] = fmaf(xv[i], w1.w, acc[i][7]);
        }
    }

    #pragma unroll
    for (int i = 0; i < 4; i++) {
        int r = row0 + ty * 4 + i;
        if (r < n) {
            float4* Cr = (float4*)(C + (size_t)r * 128);
            Cr[tx * 2]     = make_float4(acc[i][0], acc[i][1], acc[i][2], acc[i][3]);
            Cr[tx * 2 + 1] = make_float4(acc[i][4], acc[i][5], acc[i][6], acc[i][7]);
        }
    }
}

// ---------------- GEMM: C[n,40] = bnrelu(A[n,128]) @ W[128,40] ----------------
__global__ void gemm40(const float* __restrict__ A, const float* __restrict__ W,
                       float* __restrict__ C, int n) {
    __shared__ float sW[128 * 40];
    __shared__ float sX[32 * 132];

    int tid = threadIdx.x;
    int row0 = blockIdx.x * 32;

    const float4* W4  = (const float4*)W;
    float4*       sW4 = (float4*)sW;
    #pragma unroll
    for (int i = tid; i < 1280; i += 256) sW4[i] = W4[i];

    const float4* A4  = (const float4*)A + (size_t)row0 * 32;
    float4*       sX4 = (float4*)sX;
    #pragma unroll
    for (int i = tid; i < 1024; i += 256) {
        int r = i >> 5, c4 = i & 31;
        float4 v = make_float4(0.f, 0.f, 0.f, 0.f);
        if (row0 + r < n) v = A4[i];
        v = bnrelu4(v, c4);
        sX4[r * 33 + c4] = v;
    }
    __syncthreads();

    int tx = tid & 7, rt = tid >> 3;
    float acc[5] = {0.f, 0.f, 0.f, 0.f, 0.f};
    #pragma unroll 4
    for (int k = 0; k < 128; k++) {
        float xv = sX[rt * 132 + k];
        #pragma unroll
        for (int j = 0; j < 5; j++)
            acc[j] = fmaf(xv, sW[k * 40 + tx * 5 + j], acc[j]);
    }
    int row = row0 + rt;
    if (row < n) {
        #pragma unroll
        for (int j = 0; j < 5; j++)
            C[(size_t)row * 40 + tx * 5 + j] = acc[j];
    }
}

// ---------------- CSR gather (D=128) + self-loop + bias + BN stats ----------------
__global__ void gather128_bn(const float* __restrict__ xw, const float* __restrict__ b,
                             float* __restrict__ h, int n) {
    __shared__ float sbs[128], sbss[128];
    int tid = threadIdx.x;
    if (tid < 128) { sbs[tid] = 0.f; sbss[tid] = 0.f; }
    __syncthreads();

    int lane   = tid & 31;
    int warp   = (blockIdx.x * blockDim.x + tid) >> 5;
    int nwarps = (gridDim.x * blockDim.x) >> 5;

    float4 ps  = make_float4(0.f, 0.f, 0.f, 0.f);
    float4 pss = make_float4(0.f, 0.f, 0.f, 0.f);
    float4 bb  = ((const float4*)b)[lane];

    for (int v = warp; v < n; v += nwarps) {
        int beg = g_rowptr[v], end = g_rowptr[v + 1];
        float4 acc = make_float4(0.f, 0.f, 0.f, 0.f);
        for (int i = beg; i < end; i++) {
            int   s = g_esrc[i];
            float w = g_enorm[i];
            float4 xv = ((const float4*)(xw + (size_t)s * D))[lane];
            acc.x = fmaf(xv.x, w, acc.x);
            acc.y = fmaf(xv.y, w, acc.y);
            acc.z = fmaf(xv.z, w, acc.z);
            acc.w = fmaf(xv.w, w, acc.w);
        }
        float di  = g_dinv[v];
        float di2 = di * di;
        float4 xv = ((const float4*)(xw + (size_t)v * D))[lane];
        acc.x = fmaf(xv.x, di2, acc.x) + bb.x;
        acc.y = fmaf(xv.y, di2, acc.y) + bb.y;
        acc.z = fmaf(xv.z, di2, acc.z) + bb.z;
        acc.w = fmaf(xv.w, di2, acc.w) + bb.w;
        ((float4*)(h + (size_t)v * D))[lane] = acc;
        ps.x += acc.x; ps.y += acc.y; ps.z += acc.z; ps.w += acc.w;
        pss.x = fmaf(acc.x, acc.x, pss.x);
        pss.y = fmaf(acc.y, acc.y, pss.y);
        pss.z = fmaf(acc.z, acc.z, pss.z);
        pss.w = fmaf(acc.w, acc.w, pss.w);
    }

    atomicAdd(&sbs[lane * 4 + 0], ps.x);
    atomicAdd(&sbs[lane * 4 + 1], ps.y);
    atomicAdd(&sbs[lane * 4 + 2], ps.z);
    atomicAdd(&sbs[lane * 4 + 3], ps.w);
    atomicAdd(&sbss[lane * 4 + 0], pss.x);
    atomicAdd(&sbss[lane * 4 + 1], pss.y);
    atomicAdd(&sbss[lane * 4 + 2], pss.z);
    atomicAdd(&sbss[lane * 4 + 3], pss.w);
    __syncthreads();
    if (tid < 128) {
        atomicAdd(&g_bnsum[tid],   sbs[tid]);
        atomicAdd(&g_bnsumsq[tid], sbss[tid]);
    }
}

__global__ void bn_final(const float* __restrict__ g, const float* __restrict__ be,
                         float fn) {
    int c = threadIdx.x;
    float mean = g_bnsum[c] / fn;
    float var  = g_bnsumsq[c] / fn - mean * mean;
    float sc   = g[c] * rsqrtf(var + 1e-5f);
    g_scale[c] = sc;
    g_shift[c] = be[c] - mean * sc;
}

// ---------------- CSR gather (D=40) + self-loop + bias + log_softmax ----------------
__global__ void gather40_softmax(const float* __restrict__ b2, float* __restrict__ out,
                                 int n) {
    int lane   = threadIdx.x & 31;
    int warp   = (blockIdx.x * blockDim.x + threadIdx.x) >> 5;
    int nwarps = (gridDim.x * blockDim.x) >> 5;

    for (int v = warp; v < n; v += nwarps) {
        int beg = g_rowptr[v], end = g_rowptr[v + 1];
        float4 acc = make_float4(0.f, 0.f, 0.f, 0.f);
        if (lane < 10) {
            for (int i = beg; i < end; i++) {
                int   s = g_esrc[i];
                float w = g_enorm[i];
                float4 xv = ((const float4*)(g_xw2 + (size_t)s * DOUT))[lane];
                acc.x = fmaf(xv.x, w, acc.x);
                acc.y = fmaf(xv.y, w, acc.y);
                acc.z = fmaf(xv.z, w, acc.z);
                acc.w = fmaf(xv.w, w, acc.w);
            }
            float di  = g_dinv[v];
            float di2 = di * di;
            float4 xv = ((const float4*)(g_xw2 + (size_t)v * DOUT))[lane];
            float4 bb = ((const float4*)b2)[lane];
            acc.x = fmaf(xv.x, di2, acc.x) + bb.x;
            acc.y = fmaf(xv.y, di2, acc.y) + bb.y;
            acc.z = fmaf(xv.z, di2, acc.z) + bb.z;
            acc.w = fmaf(xv.w, di2, acc.w) + bb.w;
        }
        float m = (lane < 10)
                ? fmaxf(fmaxf(acc.x, acc.y), fmaxf(acc.z, acc.w)) : -1e30f;
        #pragma unroll
        for (int o = 16; o; o >>= 1) m = fmaxf(m, __shfl_xor_sync(0xffffffffu, m, o));
        float s = (lane < 10)
                ? (expf(acc.x - m) + expf(acc.y - m) + expf(acc.z - m) + expf(acc.w - m))
                : 0.f;
        #pragma unroll
        for (int o = 16; o; o >>= 1) s += __shfl_xor_sync(0xffffffffu, s, o);
        float lse = m + logf(s);
        if (lane < 10)
            ((float4*)(out + (size_t)v * DOUT))[lane] =
                make_float4(acc.x - lse, acc.y - lse, acc.z - lse, acc.w - lse);
    }
}

// ---------------- launch ----------------
extern "C" void kernel_launch(void* const* d_in, const int* in_sizes, int n_in,
                              void* d_out, int out_size) {
    const float* x   = (const float*)d_in[0];
    const void*  ei  = d_in[1];
    const float* ew  = (const float*)d_in[2];
    const float* W0  = (const float*)d_in[3];
    const float* b0  = (const float*)d_in[4];
    const float* g0  = (const float*)d_in[5];
    const float* be0 = (const float*)d_in[6];
    const float* W1  = (const float*)d_in[7];
    const float* b1  = (const float*)d_in[8];
    const float* g1  = (const float*)d_in[9];
    const float* be1 = (const float*)d_in[10];
    const float* W2  = (const float*)d_in[11];
    const float* b2  = (const float*)d_in[12];

    int n = in_sizes[0] / D;
    int E = in_sizes[2];
    int twoE = 2 * E;

    cudaFuncSetAttribute(gemm128<false>, cudaFuncAttributeMaxDynamicSharedMemorySize, GEMM_SMEM);
    cudaFuncSetAttribute(gemm128<true>,  cudaFuncAttributeMaxDynamicSharedMemorySize, GEMM_SMEM);

    void *p_deg, *p_cnt, *p_fill, *p_bns, *p_bnss, *p_xw, *p_h, *p_xw2;
    cudaGetSymbolAddress(&p_deg,  g_deg);
    cudaGetSymbolAddress(&p_cnt,  g_cnt);
    cudaGetSymbolAddress(&p_fill, g_fill);
    cudaGetSymbolAddress(&p_bns,  g_bnsum);
    cudaGetSymbolAddress(&p_bnss, g_bnsumsq);
    cudaGetSymbolAddress(&p_xw,   g_xw);
    cudaGetSymbolAddress(&p_h,    g_h);
    cudaGetSymbolAddress(&p_xw2,  g_xw2);
    float* xw  = (float*)p_xw;
    float* h   = (float*)p_h;
    float* xw2 = (float*)p_xw2;

    const int T = 256;
    int nb_scan = cdiv(n, 512);
    int gather_blocks = 1184;   // 148 SMs * 8 blocks, grid-stride warps

    // ---- index convert + CSR build (amortized over 3 aggregations) ----
    detect_kernel<<<1, 32>>>((const unsigned*)ei, twoE);
    convert_kernel<<<cdiv(twoE, T), T>>>(ei, twoE);
    cudaMemsetAsync(p_deg,  0, (size_t)n * sizeof(float), 0);
    cudaMemsetAsync(p_cnt,  0, (size_t)n * sizeof(int), 0);
    cudaMemsetAsync(p_fill, 0, (size_t)n * sizeof(int), 0);
    degcnt_kernel<<<cdiv(E, T), T>>>(ew, E);
    dinv_kernel<<<cdiv(n, T), T>>>(n);
    scan1<<<nb_scan, 512>>>(n);
    scan2<<<1, 256>>>(nb_scan);
    scan3<<<cdiv(n, T), T>>>(n, E);
    fill_kernel<<<cdiv(E, T), T>>>(ew, E);

    // ---- layer 0 ----
    gemm128<false><<<cdiv(n, 64), T, GEMM_SMEM>>>(x, W0, xw, n);
    cudaMemsetAsync(p_bns, 0, D * sizeof(float), 0);
    cudaMemsetAsync(p_bnss, 0, D * sizeof(float), 0);
    gather128_bn<<<gather_blocks, T>>>(xw, b0, h, n);
    bn_final<<<1, D>>>(g0, be0, (float)n);

    // ---- layer 1 ----
    gemm128<true><<<cdiv(n, 64), T, GEMM_SMEM>>>(h, W1, xw, n);
    cudaMemsetAsync(p_bns, 0, D * sizeof(float), 0);
    cudaMemsetAsync(p_bnss, 0, D * sizeof(float), 0);
    gather128_bn<<<gather_blocks, T>>>(xw, b1, h, n);
    bn_final<<<1, D>>>(g1, be1, (float)n);

    // ---- layer 2 + log_softmax ----
    gemm40<<<cdiv(n, 32), T>>>(h, W2, xw2, n);
    gather40_softmax<<<gather_blocks, T>>>(b2, (float*)d_out, n);
}

// round 5
// speedup vs baseline: 1.3649x; 1.0092x over previous
#include <cuda_runtime.h>
#include <math.h>

#define D    128
#define DOUT 40
#define NMAX 100000
#define EMAX 1600000

typedef unsigned long long ull;

static inline int cdiv(int a, int b) { return (a + b - 1) / b; }

// ---------------- scratch (static device globals; no allocation) ----------------
__device__ __align__(16) float g_xw  [(size_t)NMAX * D];
__device__ __align__(16) float g_h   [(size_t)NMAX * D];
__device__ __align__(16) float g_xw2 [(size_t)NMAX * DOUT];
__device__ float g_deg [NMAX];
__device__ float g_dinv[NMAX];
__device__ int   g_idx [2 * EMAX];     // converted int32 src|dst
__device__ int   g_is64;
// CSR
__device__ int   g_cnt [NMAX];
__device__ int   g_rowptr[NMAX + 1];
__device__ int   g_fill[NMAX];
__device__ int   g_bsum[256];
__device__ int   g_boff[256];
__device__ int   g_esrc [EMAX];
__device__ float g_enorm[EMAX];
// BN
__device__ __align__(16) float g_bnsum  [D];
__device__ __align__(16) float g_bnsumsq[D];
__device__ __align__(16) float g_scale  [D];
__device__ __align__(16) float g_shift  [D];

// ---------------- packed f32x2 helpers (Blackwell FFMA2 path) ----------------
__device__ __forceinline__ ull fma2(ull a, ull b, ull c) {
    ull d;
    asm("fma.rn.f32x2 %0, %1, %2, %3;" : "=l"(d) : "l"(a), "l"(b), "l"(c));
    return d;
}
__device__ __forceinline__ ull splat2(float x) {
    ull d;
    asm("mov.b64 %0, {%1, %1};" : "=l"(d) : "f"(x));
    return d;
}

// ---------------- index dtype detect + convert ----------------
__global__ void detect_kernel(const unsigned* __restrict__ w, int twoE) {
    if (threadIdx.x == 0 && blockIdx.x == 0) {
        int nchk = twoE < 256 ? twoE : 256;
        int is64 = 1;
        for (int i = 0; i < nchk; i++)
            if (w[2 * i + 1] != 0u) { is64 = 0; break; }
        g_is64 = is64;
    }
}

__global__ void convert_kernel(const void* __restrict__ ei, int twoE) {
    int i = blockIdx.x * blockDim.x + threadIdx.x;
    if (i < twoE) {
        int v;
        if (g_is64) v = (int)((const long long*)ei)[i];
        else        v = ((const int*)ei)[i];
        g_idx[i] = v;
    }
}

// ---------------- degree (weighted) + dst histogram ----------------
__global__ void degcnt_kernel(const float* __restrict__ ew, int E) {
    int e = blockIdx.x * blockDim.x + threadIdx.x;
    if (e < E) {
        int d = g_idx[E + e];
        atomicAdd(&g_deg[d], ew[e]);
        atomicAdd(&g_cnt[d], 1);
    }
}

// ---------------- exclusive scan of g_cnt -> g_rowptr (3-pass) ----------------
__global__ void scan1(int n) {
    __shared__ int sm[512];
    int i = blockIdx.x * 512 + threadIdx.x;
    int v = (i < n) ? g_cnt[i] : 0;
    sm[threadIdx.x] = v;
    __syncthreads();
    #pragma unroll
    for (int o = 1; o < 512; o <<= 1) {
        int t = (threadIdx.x >= o) ? sm[threadIdx.x - o] : 0;
        __syncthreads();
        sm[threadIdx.x] += t;
        __syncthreads();
    }
    if (i < n) g_rowptr[i] = sm[threadIdx.x] - v;
    if (threadIdx.x == 511) g_bsum[blockIdx.x] = sm[511];
}

__global__ void scan2(int nb) {
    __shared__ int sm[256];
    int v = (threadIdx.x < nb) ? g_bsum[threadIdx.x] : 0;
    sm[threadIdx.x] = v;
    __syncthreads();
    #pragma unroll
    for (int o = 1; o < 256; o <<= 1) {
        int t = (threadIdx.x >= o) ? sm[threadIdx.x - o] : 0;
        __syncthreads();
        sm[threadIdx.x] += t;
        __syncthreads();
    }
    if (threadIdx.x < nb) g_boff[threadIdx.x] = sm[threadIdx.x] - v;
}

// scan finalize + dinv (fused)
__global__ void scan3(int n, int E) {
    int i = blockIdx.x * blockDim.x + threadIdx.x;
    if (i < n) {
        g_rowptr[i] += g_boff[i >> 9];
        g_dinv[i] = rsqrtf(g_deg[i] + 1.0f);
    }
    if (i == 0) g_rowptr[n] = E;
}

// ---------------- CSR fill (also computes per-edge norm) ----------------
__global__ void fill_kernel(const float* __restrict__ ew, int E) {
    int e = blockIdx.x * blockDim.x + threadIdx.x;
    if (e < E) {
        int s = g_idx[e];
        int d = g_idx[E + e];
        int pos = g_rowptr[d] + atomicAdd(&g_fill[d], 1);
        g_esrc[pos]  = s;
        g_enorm[pos] = g_dinv[s] * ew[e] * g_dinv[d];
    }
}

// ---------------- fused BN+ReLU on load ----------------
__device__ __forceinline__ float4 bnrelu4(float4 v, int c4) {
    float4 sc = ((const float4*)g_scale)[c4];
    float4 sh = ((const float4*)g_shift)[c4];
    v.x = fmaxf(fmaf(v.x, sc.x, sh.x), 0.0f);
    v.y = fmaxf(fmaf(v.y, sc.y, sh.y), 0.0f);
    v.z = fmaxf(fmaf(v.z, sc.z, sh.z), 0.0f);
    v.w = fmaxf(fmaf(v.w, sc.w, sh.w), 0.0f);
    return v;
}

// ---------------- GEMM: C[n,128] = act(A[n,128]) @ W[128,128] ----------------
// 256 threads, 64 rows x 128 cols per block; packed f32x2 accumulators.
#define GEMM_SMEM ((128 * 128 + 64 * 132) * 4)

template <bool FUSE_BN>
__global__ void gemm128(const float* __restrict__ A, const float* __restrict__ W,
                        float* __restrict__ C, int n) {
    extern __shared__ float smem[];
    float* sW = smem;                 // [128][128]
    float* sX = smem + 128 * 128;     // [64][132] padded

    int tid = threadIdx.x;
    int row0 = blockIdx.x * 64;

    const float4* W4  = (const float4*)W;
    float4*       sW4 = (float4*)sW;
    #pragma unroll
    for (int i = tid; i < 4096; i += 256) sW4[i] = W4[i];

    const float4* A4  = (const float4*)A + (size_t)row0 * 32;
    float4*       sX4 = (float4*)sX;
    #pragma unroll
    for (int i = tid; i < 2048; i += 256) {
        int r = i >> 5, c4 = i & 31;
        float4 v = make_float4(0.f, 0.f, 0.f, 0.f);
        if (row0 + r < n) v = A4[i];
        if (FUSE_BN) v = bnrelu4(v, c4);
        sX4[r * 33 + c4] = v;
    }
    __syncthreads();

    int tx = tid & 15, ty = tid >> 4;   // cols = tx*8 .. tx*8+7 ; rows = ty*4 + i
    ull acc[4][4];
    #pragma unroll
    for (int i = 0; i < 4; i++)
        #pragma unroll
        for (int p = 0; p < 4; p++) acc[i][p] = splat2(0.f);

    // row k of sW = 128 floats = 32 ulonglong2; thread tx owns ull2 idx 2tx, 2tx+1
    const ulonglong2* sW2 = (const ulonglong2*)sW;
    #pragma unroll 4
    for (int k = 0; k < 128; k++) {
        ulonglong2 wa = sW2[k * 32 + 2 * tx];
        ulonglong2 wb = sW2[k * 32 + 2 * tx + 1];
        #pragma unroll
        for (int i = 0; i < 4; i++) {
            ull xi = splat2(sX[(ty * 4 + i) * 132 + k]);
            acc[i][0] = fma2(xi, wa.x, acc[i][0]);
            acc[i][1] = fma2(xi, wa.y, acc[i][1]);
            acc[i][2] = fma2(xi, wb.x, acc[i][2]);
            acc[i][3] = fma2(xi, wb.y, acc[i][3]);
        }
    }

    #pragma unroll
    for (int i = 0; i < 4; i++) {
        int r = row0 + ty * 4 + i;
        if (r < n) {
            ulonglong2* Cr = (ulonglong2*)(C + (size_t)r * 128);
            ulonglong2 v0; v0.x = acc[i][0]; v0.y = acc[i][1];
            ulonglong2 v1; v1.x = acc[i][2]; v1.y = acc[i][3];
            Cr[2 * tx]     = v0;
            Cr[2 * tx + 1] = v1;
        }
    }
}

// ---------------- GEMM: C[n,40] = bnrelu(A[n,128]) @ W[128,40] ----------------
__global__ void gemm40(const float* __restrict__ A, const float* __restrict__ W,
                       float* __restrict__ C, int n) {
    __shared__ float sW[128 * 40];
    __shared__ float sX[32 * 132];

    int tid = threadIdx.x;
    int row0 = blockIdx.x * 32;

    const float4* W4  = (const float4*)W;
    float4*       sW4 = (float4*)sW;
    #pragma unroll
    for (int i = tid; i < 1280; i += 256) sW4[i] = W4[i];

    const float4* A4  = (const float4*)A + (size_t)row0 * 32;
    float4*       sX4 = (float4*)sX;
    #pragma unroll
    for (int i = tid; i < 1024; i += 256) {
        int r = i >> 5, c4 = i & 31;
        float4 v = make_float4(0.f, 0.f, 0.f, 0.f);
        if (row0 + r < n) v = A4[i];
        v = bnrelu4(v, c4);
        sX4[r * 33 + c4] = v;
    }
    __syncthreads();

    int tx = tid & 7, rt = tid >> 3;
    float acc[5] = {0.f, 0.f, 0.f, 0.f, 0.f};
    #pragma unroll 4
    for (int k = 0; k < 128; k++) {
        float xv = sX[rt * 132 + k];
        #pragma unroll
        for (int j = 0; j < 5; j++)
            acc[j] = fmaf(xv, sW[k * 40 + tx * 5 + j], acc[j]);
    }
    int row = row0 + rt;
    if (row < n) {
        #pragma unroll
        for (int j = 0; j < 5; j++)
            C[(size_t)row * 40 + tx * 5 + j] = acc[j];
    }
}

// ---------------- CSR gather (D=128) + self-loop + bias + BN stats ----------------
__global__ void gather128_bn(const float* __restrict__ xw, const float* __restrict__ b,
                             float* __restrict__ h, int n) {
    __shared__ float sbs[128], sbss[128];
    int tid = threadIdx.x;
    if (tid < 128) { sbs[tid] = 0.f; sbss[tid] = 0.f; }
    __syncthreads();

    int lane   = tid & 31;
    int warp   = (blockIdx.x * blockDim.x + tid) >> 5;
    int nwarps = (gridDim.x * blockDim.x) >> 5;

    float4 ps  = make_float4(0.f, 0.f, 0.f, 0.f);
    float4 pss = make_float4(0.f, 0.f, 0.f, 0.f);
    float4 bb  = ((const float4*)b)[lane];

    for (int v = warp; v < n; v += nwarps) {
        int beg = g_rowptr[v], end = g_rowptr[v + 1];
        float4 acc = make_float4(0.f, 0.f, 0.f, 0.f);
        for (int i = beg; i < end; i++) {
            int   s = g_esrc[i];
            float w = g_enorm[i];
            float4 xv = ((const float4*)(xw + (size_t)s * D))[lane];
            acc.x = fmaf(xv.x, w, acc.x);
            acc.y = fmaf(xv.y, w, acc.y);
            acc.z = fmaf(xv.z, w, acc.z);
            acc.w = fmaf(xv.w, w, acc.w);
        }
        float di  = g_dinv[v];
        float di2 = di * di;
        float4 xv = ((const float4*)(xw + (size_t)v * D))[lane];
        acc.x = fmaf(xv.x, di2, acc.x) + bb.x;
        acc.y = fmaf(xv.y, di2, acc.y) + bb.y;
        acc.z = fmaf(xv.z, di2, acc.z) + bb.z;
        acc.w = fmaf(xv.w, di2, acc.w) + bb.w;
        ((float4*)(h + (size_t)v * D))[lane] = acc;
        ps.x += acc.x; ps.y += acc.y; ps.z += acc.z; ps.w += acc.w;
        pss.x = fmaf(acc.x, acc.x, pss.x);
        pss.y = fmaf(acc.y, acc.y, pss.y);
        pss.z = fmaf(acc.z, acc.z, pss.z);
        pss.w = fmaf(acc.w, acc.w, pss.w);
    }

    atomicAdd(&sbs[lane * 4 + 0], ps.x);
    atomicAdd(&sbs[lane * 4 + 1], ps.y);
    atomicAdd(&sbs[lane * 4 + 2], ps.z);
    atomicAdd(&sbs[lane * 4 + 3], ps.w);
    atomicAdd(&sbss[lane * 4 + 0], pss.x);
    atomicAdd(&sbss[lane * 4 + 1], pss.y);
    atomicAdd(&sbss[lane * 4 + 2], pss.z);
    atomicAdd(&sbss[lane * 4 + 3], pss.w);
    __syncthreads();
    if (tid < 128) {
        atomicAdd(&g_bnsum[tid],   sbs[tid]);
        atomicAdd(&g_bnsumsq[tid], sbss[tid]);
    }
}

__global__ void bn_final(const float* __restrict__ g, const float* __restrict__ be,
                         float fn) {
    int c = threadIdx.x;
    float mean = g_bnsum[c] / fn;
    float var  = g_bnsumsq[c] / fn - mean * mean;
    float sc   = g[c] * rsqrtf(var + 1e-5f);
    g_scale[c] = sc;
    g_shift[c] = be[c] - mean * sc;
}

// ---------------- CSR gather (D=40) + self-loop + bias + log_softmax ----------------
__global__ void gather40_softmax(const float* __restrict__ b2, float* __restrict__ out,
                                 int n) {
    int lane   = threadIdx.x & 31;
    int warp   = (blockIdx.x * blockDim.x + threadIdx.x) >> 5;
    int nwarps = (gridDim.x * blockDim.x) >> 5;

    for (int v = warp; v < n; v += nwarps) {
        int beg = g_rowptr[v], end = g_rowptr[v + 1];
        float4 acc = make_float4(0.f, 0.f, 0.f, 0.f);
        if (lane < 10) {
            for (int i = beg; i < end; i++) {
                int   s = g_esrc[i];
                float w = g_enorm[i];
                float4 xv = ((const float4*)(g_xw2 + (size_t)s * DOUT))[lane];
                acc.x = fmaf(xv.x, w, acc.x);
                acc.y = fmaf(xv.y, w, acc.y);
                acc.z = fmaf(xv.z, w, acc.z);
                acc.w = fmaf(xv.w, w, acc.w);
            }
            float di  = g_dinv[v];
            float di2 = di * di;
            float4 xv = ((const float4*)(g_xw2 + (size_t)v * DOUT))[lane];
            float4 bb = ((const float4*)b2)[lane];
            acc.x = fmaf(xv.x, di2, acc.x) + bb.x;
            acc.y = fmaf(xv.y, di2, acc.y) + bb.y;
            acc.z = fmaf(xv.z, di2, acc.z) + bb.z;
            acc.w = fmaf(xv.w, di2, acc.w) + bb.w;
        }
        float m = (lane < 10)
                ? fmaxf(fmaxf(acc.x, acc.y), fmaxf(acc.z, acc.w)) : -1e30f;
        #pragma unroll
        for (int o = 16; o; o >>= 1) m = fmaxf(m, __shfl_xor_sync(0xffffffffu, m, o));
        float s = (lane < 10)
                ? (expf(acc.x - m) + expf(acc.y - m) + expf(acc.z - m) + expf(acc.w - m))
                : 0.f;
        #pragma unroll
        for (int o = 16; o; o >>= 1) s += __shfl_xor_sync(0xffffffffu, s, o);
        float lse = m + logf(s);
        if (lane < 10)
            ((float4*)(out + (size_t)v * DOUT))[lane] =
                make_float4(acc.x - lse, acc.y - lse, acc.z - lse, acc.w - lse);
    }
}

// ---------------- launch ----------------
extern "C" void kernel_launch(void* const* d_in, const int* in_sizes, int n_in,
                              void* d_out, int out_size) {
    const float* x   = (const float*)d_in[0];
    const void*  ei  = d_in[1];
    const float* ew  = (const float*)d_in[2];
    const float* W0  = (const float*)d_in[3];
    const float* b0  = (const float*)d_in[4];
    const float* g0  = (const float*)d_in[5];
    const float* be0 = (const float*)d_in[6];
    const float* W1  = (const float*)d_in[7];
    const float* b1  = (const float*)d_in[8];
    const float* g1  = (const float*)d_in[9];
    const float* be1 = (const float*)d_in[10];
    const float* W2  = (const float*)d_in[11];
    const float* b2  = (const float*)d_in[12];

    int n = in_sizes[0] / D;
    int E = in_sizes[2];
    int twoE = 2 * E;

    cudaFuncSetAttribute(gemm128<false>, cudaFuncAttributeMaxDynamicSharedMemorySize, GEMM_SMEM);
    cudaFuncSetAttribute(gemm128<true>,  cudaFuncAttributeMaxDynamicSharedMemorySize, GEMM_SMEM);

    void *p_deg, *p_cnt, *p_fill, *p_bns, *p_bnss, *p_xw, *p_h, *p_xw2;
    cudaGetSymbolAddress(&p_deg,  g_deg);
    cudaGetSymbolAddress(&p_cnt,  g_cnt);
    cudaGetSymbolAddress(&p_fill, g_fill);
    cudaGetSymbolAddress(&p_bns,  g_bnsum);
    cudaGetSymbolAddress(&p_bnss, g_bnsumsq);
    cudaGetSymbolAddress(&p_xw,   g_xw);
    cudaGetSymbolAddress(&p_h,    g_h);
    cudaGetSymbolAddress(&p_xw2,  g_xw2);
    float* xw  = (float*)p_xw;
    float* h   = (float*)p_h;
    float* xw2 = (float*)p_xw2;

    const int T = 256;
    int nb_scan = cdiv(n, 512);
    int gather_blocks = 1184;   // 148 SMs * 8 blocks, grid-stride warps

    // ---- index convert + CSR build (amortized over 3 aggregations) ----
    detect_kernel<<<1, 32>>>((const unsigned*)ei, twoE);
    convert_kernel<<<cdiv(twoE, T), T>>>(ei, twoE);
    cudaMemsetAsync(p_deg,  0, (size_t)n * sizeof(float), 0);
    cudaMemsetAsync(p_cnt,  0, (size_t)n * sizeof(int), 0);
    cudaMemsetAsync(p_fill, 0, (size_t)n * sizeof(int), 0);
    degcnt_kernel<<<cdiv(E, T), T>>>(ew, E);
    scan1<<<nb_scan, 512>>>(n);
    scan2<<<1, 256>>>(nb_scan);
    scan3<<<cdiv(n, T), T>>>(n, E);
    fill_kernel<<<cdiv(E, T), T>>>(ew, E);

    // ---- layer 0 ----
    gemm128<false><<<cdiv(n, 64), T, GEMM_SMEM>>>(x, W0, xw, n);
    cudaMemsetAsync(p_bns, 0, D * sizeof(float), 0);
    cudaMemsetAsync(p_bnss, 0, D * sizeof(float), 0);
    gather128_bn<<<gather_blocks, T>>>(xw, b0, h, n);
    bn_final<<<1, D>>>(g0, be0, (float)n);

    // ---- layer 1 ----
    gemm128<true><<<cdiv(n, 64), T, GEMM_SMEM>>>(h, W1, xw, n);
    cudaMemsetAsync(p_bns, 0, D * sizeof(float), 0);
    cudaMemsetAsync(p_bnss, 0, D * sizeof(float), 0);
    gather128_bn<<<gather_blocks, T>>>(xw, b1, h, n);
    bn_final<<<1, D>>>(g1, be1, (float)n);

    // ---- layer 2 + log_softmax ----
    gemm40<<<cdiv(n, 32), T>>>(h, W2, xw2, n);
    gather40_softmax<<<gather_blocks, T>>>(b2, (float*)d_out, n);
}

// round 6
// speedup vs baseline: 1.7324x; 1.2692x over previous
#include <cuda_runtime.h>
#include <cuda_fp16.h>
#include <math.h>

#define D    128
#define DOUT 40
#define NMAX 100000
#define EMAX 1600000

typedef unsigned long long ull;

static inline int cdiv(int a, int b) { return (a + b - 1) / b; }

// ---------------- scratch (static device globals; no allocation) ----------------
__device__ __align__(16) __half g_xw [(size_t)NMAX * D];   // fp16: gather operand
__device__ __align__(16) float g_h   [(size_t)NMAX * D];
__device__ __align__(16) float g_xw2 [(size_t)NMAX * DOUT];
__device__ float g_deg [NMAX];
__device__ float g_dinv[NMAX];
__device__ int   g_idx [2 * EMAX];     // converted int32 src|dst
__device__ int   g_is64;
// CSR
__device__ int   g_cnt [NMAX];
__device__ int   g_rowptr[NMAX + 1];
__device__ int   g_fill[NMAX];
__device__ int   g_bsum[256];
__device__ int   g_boff[256];
__device__ int   g_esrc [EMAX];
__device__ float g_enorm[EMAX];
// BN
__device__ __align__(16) float g_bnsum  [D];
__device__ __align__(16) float g_bnsumsq[D];
__device__ __align__(16) float g_scale  [D];
__device__ __align__(16) float g_shift  [D];

// ---------------- packed f32x2 helpers ----------------
__device__ __forceinline__ ull fma2(ull a, ull b, ull c) {
    ull d;
    asm("fma.rn.f32x2 %0, %1, %2, %3;" : "=l"(d) : "l"(a), "l"(b), "l"(c));
    return d;
}
__device__ __forceinline__ ull splat2(float x) {
    ull d;
    asm("mov.b64 %0, {%1, %1};" : "=l"(d) : "f"(x));
    return d;
}

// ---------------- index dtype detect + convert ----------------
__global__ void detect_kernel(const unsigned* __restrict__ w, int twoE) {
    if (threadIdx.x == 0 && blockIdx.x == 0) {
        int nchk = twoE < 256 ? twoE : 256;
        int is64 = 1;
        for (int i = 0; i < nchk; i++)
            if (w[2 * i + 1] != 0u) { is64 = 0; break; }
        g_is64 = is64;
    }
}

__global__ void convert_kernel(const void* __restrict__ ei, int twoE) {
    int i = blockIdx.x * blockDim.x + threadIdx.x;
    if (i < twoE) {
        int v;
        if (g_is64) v = (int)((const long long*)ei)[i];
        else        v = ((const int*)ei)[i];
        g_idx[i] = v;
    }
}

// ---------------- degree (weighted) + dst histogram ----------------
__global__ void degcnt_kernel(const float* __restrict__ ew, int E) {
    int e = blockIdx.x * blockDim.x + threadIdx.x;
    if (e < E) {
        int d = g_idx[E + e];
        atomicAdd(&g_deg[d], ew[e]);
        atomicAdd(&g_cnt[d], 1);
    }
}

// ---------------- exclusive scan of g_cnt -> g_rowptr (3-pass) ----------------
__global__ void scan1(int n) {
    __shared__ int sm[512];
    int i = blockIdx.x * 512 + threadIdx.x;
    int v = (i < n) ? g_cnt[i] : 0;
    sm[threadIdx.x] = v;
    __syncthreads();
    #pragma unroll
    for (int o = 1; o < 512; o <<= 1) {
        int t = (threadIdx.x >= o) ? sm[threadIdx.x - o] : 0;
        __syncthreads();
        sm[threadIdx.x] += t;
        __syncthreads();
    }
    if (i < n) g_rowptr[i] = sm[threadIdx.x] - v;
    if (threadIdx.x == 511) g_bsum[blockIdx.x] = sm[511];
}

__global__ void scan2(int nb) {
    __shared__ int sm[256];
    int v = (threadIdx.x < nb) ? g_bsum[threadIdx.x] : 0;
    sm[threadIdx.x] = v;
    __syncthreads();
    #pragma unroll
    for (int o = 1; o < 256; o <<= 1) {
        int t = (threadIdx.x >= o) ? sm[threadIdx.x - o] : 0;
        __syncthreads();
        sm[threadIdx.x] += t;
        __syncthreads();
    }
    if (threadIdx.x < nb) g_boff[threadIdx.x] = sm[threadIdx.x] - v;
}

// scan finalize + dinv (fused)
__global__ void scan3(int n, int E) {
    int i = blockIdx.x * blockDim.x + threadIdx.x;
    if (i < n) {
        g_rowptr[i] += g_boff[i >> 9];
        g_dinv[i] = rsqrtf(g_deg[i] + 1.0f);
    }
    if (i == 0) g_rowptr[n] = E;
}

// ---------------- CSR fill (also computes per-edge norm) ----------------
__global__ void fill_kernel(const float* __restrict__ ew, int E) {
    int e = blockIdx.x * blockDim.x + threadIdx.x;
    if (e < E) {
        int s = g_idx[e];
        int d = g_idx[E + e];
        int pos = g_rowptr[d] + atomicAdd(&g_fill[d], 1);
        g_esrc[pos]  = s;
        g_enorm[pos] = g_dinv[s] * ew[e] * g_dinv[d];
    }
}

// ---------------- fused BN+ReLU on load ----------------
__device__ __forceinline__ float4 bnrelu4(float4 v, int c4) {
    float4 sc = ((const float4*)g_scale)[c4];
    float4 sh = ((const float4*)g_shift)[c4];
    v.x = fmaxf(fmaf(v.x, sc.x, sh.x), 0.0f);
    v.y = fmaxf(fmaf(v.y, sc.y, sh.y), 0.0f);
    v.z = fmaxf(fmaf(v.z, sc.z, sh.z), 0.0f);
    v.w = fmaxf(fmaf(v.w, sc.w, sh.w), 0.0f);
    return v;
}

// ---------------- GEMM: xw_h[n,128] = half( act(A[n,128]) @ W[128,128] ) ----------
// 256 threads, 128 rows x 128 cols per block; 8x8 per thread (row-split 4+4),
// packed f32x2 accumulators, fp16 output.
#define GEMM_SMEM ((128 * 128 + 128 * 132) * 4)

template <bool FUSE_BN>
__global__ void __launch_bounds__(256) gemm128(const float* __restrict__ A,
                                               const float* __restrict__ W,
                                               __half* __restrict__ C, int n) {
    extern __shared__ float smem[];
    float* sW = smem;                 // [128][128]
    float* sX = smem + 128 * 128;     // [128][132] padded

    int tid = threadIdx.x;
    int row0 = blockIdx.x * 128;

    const float4* W4  = (const float4*)W;
    float4*       sW4 = (float4*)sW;
    #pragma unroll
    for (int i = tid; i < 4096; i += 256) sW4[i] = W4[i];

    const float4* A4  = (const float4*)A + (size_t)row0 * 32;
    float4*       sX4 = (float4*)sX;
    #pragma unroll
    for (int i = tid; i < 4096; i += 256) {
        int r = i >> 5, c4 = i & 31;
        float4 v = make_float4(0.f, 0.f, 0.f, 0.f);
        if (row0 + r < n) v = A4[i];
        if (FUSE_BN) v = bnrelu4(v, c4);
        sX4[r * 33 + c4] = v;
    }
    __syncthreads();

    int tx = tid & 15, ty = tid >> 4;
    // rows: j<4 -> ty*4+j ; j>=4 -> 64+ty*4+(j-4)   (4-row warp spacing: no bank conflict)
    // cols: tx*8 .. tx*8+7
    ull acc[8][4];
    #pragma unroll
    for (int j = 0; j < 8; j++)
        #pragma unroll
        for (int p = 0; p < 4; p++) acc[j][p] = splat2(0.f);

    const ulonglong2* sW2 = (const ulonglong2*)sW;
    #pragma unroll 2
    for (int k = 0; k < 128; k++) {
        ulonglong2 wa = sW2[k * 32 + 2 * tx];
        ulonglong2 wb = sW2[k * 32 + 2 * tx + 1];
        #pragma unroll
        for (int j = 0; j < 8; j++) {
            int row = (j < 4) ? (ty * 4 + j) : (64 + ty * 4 + (j - 4));
            ull xi = splat2(sX[row * 132 + k]);
            acc[j][0] = fma2(xi, wa.x, acc[j][0]);
            acc[j][1] = fma2(xi, wa.y, acc[j][1]);
            acc[j][2] = fma2(xi, wb.x, acc[j][2]);
            acc[j][3] = fma2(xi, wb.y, acc[j][3]);
        }
    }

    #pragma unroll
    for (int j = 0; j < 8; j++) {
        int r = row0 + ((j < 4) ? (ty * 4 + j) : (64 + ty * 4 + (j - 4)));
        if (r < n) {
            uint4 o;
            union { ull u; float2 f; } cv;
            __half2 hh;
            cv.u = acc[j][0]; hh = __floats2half2_rn(cv.f.x, cv.f.y);
            o.x = *reinterpret_cast<unsigned*>(&hh);
            cv.u = acc[j][1]; hh = __floats2half2_rn(cv.f.x, cv.f.y);
            o.y = *reinterpret_cast<unsigned*>(&hh);
            cv.u = acc[j][2]; hh = __floats2half2_rn(cv.f.x, cv.f.y);
            o.z = *reinterpret_cast<unsigned*>(&hh);
            cv.u = acc[j][3]; hh = __floats2half2_rn(cv.f.x, cv.f.y);
            o.w = *reinterpret_cast<unsigned*>(&hh);
            ((uint4*)(C + (size_t)r * D))[tx] = o;
        }
    }
}

// ---------------- GEMM: C[n,40] = bnrelu(A[n,128]) @ W[128,40] ----------------
__global__ void gemm40(const float* __restrict__ A, const float* __restrict__ W,
                       float* __restrict__ C, int n) {
    __shared__ float sW[128 * 40];
    __shared__ float sX[32 * 132];

    int tid = threadIdx.x;
    int row0 = blockIdx.x * 32;

    const float4* W4  = (const float4*)W;
    float4*       sW4 = (float4*)sW;
    #pragma unroll
    for (int i = tid; i < 1280; i += 256) sW4[i] = W4[i];

    const float4* A4  = (const float4*)A + (size_t)row0 * 32;
    float4*       sX4 = (float4*)sX;
    #pragma unroll
    for (int i = tid; i < 1024; i += 256) {
        int r = i >> 5, c4 = i & 31;
        float4 v = make_float4(0.f, 0.f, 0.f, 0.f);
        if (row0 + r < n) v = A4[i];
        v = bnrelu4(v, c4);
        sX4[r * 33 + c4] = v;
    }
    __syncthreads();

    int tx = tid & 7, rt = tid >> 3;
    float acc[5] = {0.f, 0.f, 0.f, 0.f, 0.f};
    #pragma unroll 4
    for (int k = 0; k < 128; k++) {
        float xv = sX[rt * 132 + k];
        #pragma unroll
        for (int j = 0; j < 5; j++)
            acc[j] = fmaf(xv, sW[k * 40 + tx * 5 + j], acc[j]);
    }
    int row = row0 + rt;
    if (row < n) {
        #pragma unroll
        for (int j = 0; j < 5; j++)
            C[(size_t)row * 40 + tx * 5 + j] = acc[j];
    }
}

// ---------------- CSR gather (fp16 rows) + self-loop + bias + BN stats ----------
__global__ void gather128_bn(const __half* __restrict__ xw, const float* __restrict__ b,
                             float* __restrict__ h, int n) {
    __shared__ float sbs[128], sbss[128];
    int tid = threadIdx.x;
    if (tid < 128) { sbs[tid] = 0.f; sbss[tid] = 0.f; }
    __syncthreads();

    int lane   = tid & 31;
    int warp   = (blockIdx.x * blockDim.x + tid) >> 5;
    int nwarps = (gridDim.x * blockDim.x) >> 5;

    float4 ps  = make_float4(0.f, 0.f, 0.f, 0.f);
    float4 pss = make_float4(0.f, 0.f, 0.f, 0.f);
    float4 bb  = ((const float4*)b)[lane];   // cols lane*4 .. lane*4+3

    for (int v = warp; v < n; v += nwarps) {
        int beg = g_rowptr[v], end = g_rowptr[v + 1];
        float4 acc = make_float4(0.f, 0.f, 0.f, 0.f);
        for (int i = beg; i < end; i++) {
            int   s = g_esrc[i];
            float w = g_enorm[i];
            uint2 rv = ((const uint2*)(xw + (size_t)s * D))[lane];
            float2 f0 = __half22float2(*reinterpret_cast<__half2*>(&rv.x));
            float2 f1 = __half22float2(*reinterpret_cast<__half2*>(&rv.y));
            acc.x = fmaf(f0.x, w, acc.x);
            acc.y = fmaf(f0.y, w, acc.y);
            acc.z = fmaf(f1.x, w, acc.z);
            acc.w = fmaf(f1.y, w, acc.w);
        }
        float di  = g_dinv[v];
        float di2 = di * di;
        uint2 rv = ((const uint2*)(xw + (size_t)v * D))[lane];
        float2 f0 = __half22float2(*reinterpret_cast<__half2*>(&rv.x));
        float2 f1 = __half22float2(*reinterpret_cast<__half2*>(&rv.y));
        acc.x = fmaf(f0.x, di2, acc.x) + bb.x;
        acc.y = fmaf(f0.y, di2, acc.y) + bb.y;
        acc.z = fmaf(f1.x, di2, acc.z) + bb.z;
        acc.w = fmaf(f1.y, di2, acc.w) + bb.w;
        ((float4*)(h + (size_t)v * D))[lane] = acc;
        ps.x += acc.x; ps.y += acc.y; ps.z += acc.z; ps.w += acc.w;
        pss.x = fmaf(acc.x, acc.x, pss.x);
        pss.y = fmaf(acc.y, acc.y, pss.y);
        pss.z = fmaf(acc.z, acc.z, pss.z);
        pss.w = fmaf(acc.w, acc.w, pss.w);
    }

    atomicAdd(&sbs[lane * 4 + 0], ps.x);
    atomicAdd(&sbs[lane * 4 + 1], ps.y);
    atomicAdd(&sbs[lane * 4 + 2], ps.z);
    atomicAdd(&sbs[lane * 4 + 3], ps.w);
    atomicAdd(&sbss[lane * 4 + 0], pss.x);
    atomicAdd(&sbss[lane * 4 + 1], pss.y);
    atomicAdd(&sbss[lane * 4 + 2], pss.z);
    atomicAdd(&sbss[lane * 4 + 3], pss.w);
    __syncthreads();
    if (tid < 128) {
        atomicAdd(&g_bnsum[tid],   sbs[tid]);
        atomicAdd(&g_bnsumsq[tid], sbss[tid]);
    }
}

__global__ void bn_final(const float* __restrict__ g, const float* __restrict__ be,
                         float fn) {
    int c = threadIdx.x;
    float mean = g_bnsum[c] / fn;
    float var  = g_bnsumsq[c] / fn - mean * mean;
    float sc   = g[c] * rsqrtf(var + 1e-5f);
    g_scale[c] = sc;
    g_shift[c] = be[c] - mean * sc;
}

// ---------------- CSR gather (D=40) + self-loop + bias + log_softmax ----------------
__global__ void gather40_softmax(const float* __restrict__ b2, float* __restrict__ out,
                                 int n) {
    int lane   = threadIdx.x & 31;
    int warp   = (blockIdx.x * blockDim.x + threadIdx.x) >> 5;
    int nwarps = (gridDim.x * blockDim.x) >> 5;

    for (int v = warp; v < n; v += nwarps) {
        int beg = g_rowptr[v], end = g_rowptr[v + 1];
        float4 acc = make_float4(0.f, 0.f, 0.f, 0.f);
        if (lane < 10) {
            for (int i = beg; i < end; i++) {
                int   s = g_esrc[i];
                float w = g_enorm[i];
                float4 xv = ((const float4*)(g_xw2 + (size_t)s * DOUT))[lane];
                acc.x = fmaf(xv.x, w, acc.x);
                acc.y = fmaf(xv.y, w, acc.y);
                acc.z = fmaf(xv.z, w, acc.z);
                acc.w = fmaf(xv.w, w, acc.w);
            }
            float di  = g_dinv[v];
            float di2 = di * di;
            float4 xv = ((const float4*)(g_xw2 + (size_t)v * DOUT))[lane];
            float4 bb = ((const float4*)b2)[lane];
            acc.x = fmaf(xv.x, di2, acc.x) + bb.x;
            acc.y = fmaf(xv.y, di2, acc.y) + bb.y;
            acc.z = fmaf(xv.z, di2, acc.z) + bb.z;
            acc.w = fmaf(xv.w, di2, acc.w) + bb.w;
        }
        float m = (lane < 10)
                ? fmaxf(fmaxf(acc.x, acc.y), fmaxf(acc.z, acc.w)) : -1e30f;
        #pragma unroll
        for (int o = 16; o; o >>= 1) m = fmaxf(m, __shfl_xor_sync(0xffffffffu, m, o));
        float s = (lane < 10)
                ? (expf(acc.x - m) + expf(acc.y - m) + expf(acc.z - m) + expf(acc.w - m))
                : 0.f;
        #pragma unroll
        for (int o = 16; o; o >>= 1) s += __shfl_xor_sync(0xffffffffu, s, o);
        float lse = m + logf(s);
        if (lane < 10)
            ((float4*)(out + (size_t)v * DOUT))[lane] =
                make_float4(acc.x - lse, acc.y - lse, acc.z - lse, acc.w - lse);
    }
}

// ---------------- launch ----------------
extern "C" void kernel_launch(void* const* d_in, const int* in_sizes, int n_in,
                              void* d_out, int out_size) {
    const float* x   = (const float*)d_in[0];
    const void*  ei  = d_in[1];
    const float* ew  = (const float*)d_in[2];
    const float* W0  = (const float*)d_in[3];
    const float* b0  = (const float*)d_in[4];
    const float* g0  = (const float*)d_in[5];
    const float* be0 = (const float*)d_in[6];
    const float* W1  = (const float*)d_in[7];
    const float* b1  = (const float*)d_in[8];
    const float* g1  = (const float*)d_in[9];
    const float* be1 = (const float*)d_in[10];
    const float* W2  = (const float*)d_in[11];
    const float* b2  = (const float*)d_in[12];

    int n = in_sizes[0] / D;
    int E = in_sizes[2];
    int twoE = 2 * E;

    cudaFuncSetAttribute(gemm128<false>, cudaFuncAttributeMaxDynamicSharedMemorySize, GEMM_SMEM);
    cudaFuncSetAttribute(gemm128<true>,  cudaFuncAttributeMaxDynamicSharedMemorySize, GEMM_SMEM);

    void *p_deg, *p_cnt, *p_fill, *p_bns, *p_bnss, *p_xw, *p_h, *p_xw2;
    cudaGetSymbolAddress(&p_deg,  g_deg);
    cudaGetSymbolAddress(&p_cnt,  g_cnt);
    cudaGetSymbolAddress(&p_fill, g_fill);
    cudaGetSymbolAddress(&p_bns,  g_bnsum);
    cudaGetSymbolAddress(&p_bnss, g_bnsumsq);
    cudaGetSymbolAddress(&p_xw,   g_xw);
    cudaGetSymbolAddress(&p_h,    g_h);
    cudaGetSymbolAddress(&p_xw2,  g_xw2);
    __half* xw  = (__half*)p_xw;
    float*  h   = (float*)p_h;
    float*  xw2 = (float*)p_xw2;

    const int T = 256;
    int nb_scan = cdiv(n, 512);
    int gather_blocks = 1184;   // 148 SMs * 8 blocks, grid-stride warps

    // ---- index convert + CSR build (amortized over 3 aggregations) ----
    detect_kernel<<<1, 32>>>((const unsigned*)ei, twoE);
    convert_kernel<<<cdiv(twoE, T), T>>>(ei, twoE);
    cudaMemsetAsync(p_deg,  0, (size_t)n * sizeof(float), 0);
    cudaMemsetAsync(p_cnt,  0, (size_t)n * sizeof(int), 0);
    cudaMemsetAsync(p_fill, 0, (size_t)n * sizeof(int), 0);
    degcnt_kernel<<<cdiv(E, T), T>>>(ew, E);
    scan1<<<nb_scan, 512>>>(n);
    scan2<<<1, 256>>>(nb_scan);
    scan3<<<cdiv(n, T), T>>>(n, E);
    fill_kernel<<<cdiv(E, T), T>>>(ew, E);

    // ---- layer 0 ----
    gemm128<false><<<cdiv(n, 128), T, GEMM_SMEM>>>(x, W0, xw, n);
    cudaMemsetAsync(p_bns, 0, D * sizeof(float), 0);
    cudaMemsetAsync(p_bnss, 0, D * sizeof(float), 0);
    gather128_bn<<<gather_blocks, T>>>(xw, b0, h, n);
    bn_final<<<1, D>>>(g0, be0, (float)n);

    // ---- layer 1 ----
    gemm128<true><<<cdiv(n, 128), T, GEMM_SMEM>>>(h, W1, xw, n);
    cudaMemsetAsync(p_bns, 0, D * sizeof(float), 0);
    cudaMemsetAsync(p_bnss, 0, D * sizeof(float), 0);
    gather128_bn<<<gather_blocks, T>>>(xw, b1, h, n);
    bn_final<<<1, D>>>(g1, be1, (float)n);

    // ---- layer 2 + log_softmax ----
    gemm40<<<cdiv(n, 32), T>>>(h, W2, xw2, n);
    gather40_softmax<<<gather_blocks, T>>>(b2, (float*)d_out, n);
}

// round 7
// speedup vs baseline: 1.8007x; 1.0395x over previous
#include <cuda_runtime.h>
#include <cuda_fp16.h>
#include <math.h>

#define D    128
#define DOUT 40
#define NMAX 100000
#define EMAX 1600000

typedef unsigned long long ull;

static inline int cdiv(int a, int b) { return (a + b - 1) / b; }

// ---------------- scratch (static device globals; no allocation) ----------------
__device__ __align__(16) __half g_xw [(size_t)NMAX * D];    // fp16 gather operand
__device__ __align__(16) float  g_h  [(size_t)NMAX * D];
__device__ __align__(16) __half g_xw2[(size_t)NMAX * DOUT]; // fp16 final-layer operand
__device__ float g_deg [NMAX];
__device__ float g_dinv[NMAX];
__device__ int   g_idx [2 * EMAX];     // converted int32 src|dst
__device__ int   g_is64;
// CSR
__device__ int   g_cnt [NMAX];
__device__ int   g_rowptr[NMAX + 1];
__device__ int   g_fill[NMAX];
__device__ int   g_bsum[256];
__device__ int   g_boff[256];
__device__ int   g_esrc [EMAX];
__device__ float g_enorm[EMAX];
// BN
__device__ __align__(16) float g_bnsum  [D];
__device__ __align__(16) float g_bnsumsq[D];
__device__ __align__(16) float g_scale  [D];
__device__ __align__(16) float g_shift  [D];

// ---------------- packed f32x2 helpers ----------------
__device__ __forceinline__ ull fma2(ull a, ull b, ull c) {
    ull d;
    asm("fma.rn.f32x2 %0, %1, %2, %3;" : "=l"(d) : "l"(a), "l"(b), "l"(c));
    return d;
}
__device__ __forceinline__ ull splat2(float x) {
    ull d;
    asm("mov.b64 %0, {%1, %1};" : "=l"(d) : "f"(x));
    return d;
}

// ---------------- index dtype detect ----------------
__global__ void detect_kernel(const unsigned* __restrict__ w, int twoE) {
    if (threadIdx.x == 0 && blockIdx.x == 0) {
        int nchk = twoE < 256 ? twoE : 256;
        int is64 = 1;
        for (int i = 0; i < nchk; i++)
            if (w[2 * i + 1] != 0u) { is64 = 0; break; }
        g_is64 = is64;
    }
}

// ---------------- convert + degree/histogram (fused) ----------------
__global__ void convert_deg_kernel(const void* __restrict__ ei,
                                   const float* __restrict__ ew, int E) {
    int i = blockIdx.x * blockDim.x + threadIdx.x;
    int twoE = 2 * E;
    if (i < twoE) {
        int v;
        if (g_is64) v = (int)((const long long*)ei)[i];
        else        v = ((const int*)ei)[i];
        g_idx[i] = v;
        if (i >= E) {   // dst entry
            atomicAdd(&g_deg[v], ew[i - E]);
            atomicAdd(&g_cnt[v], 1);
        }
    }
}

// ---------------- exclusive scan of g_cnt -> g_rowptr (3-pass) ----------------
__global__ void scan1(int n) {
    __shared__ int sm[512];
    int i = blockIdx.x * 512 + threadIdx.x;
    int v = (i < n) ? g_cnt[i] : 0;
    sm[threadIdx.x] = v;
    __syncthreads();
    #pragma unroll
    for (int o = 1; o < 512; o <<= 1) {
        int t = (threadIdx.x >= o) ? sm[threadIdx.x - o] : 0;
        __syncthreads();
        sm[threadIdx.x] += t;
        __syncthreads();
    }
    if (i < n) g_rowptr[i] = sm[threadIdx.x] - v;
    if (threadIdx.x == 511) g_bsum[blockIdx.x] = sm[511];
}

__global__ void scan2(int nb) {
    __shared__ int sm[256];
    int v = (threadIdx.x < nb) ? g_bsum[threadIdx.x] : 0;
    sm[threadIdx.x] = v;
    __syncthreads();
    #pragma unroll
    for (int o = 1; o < 256; o <<= 1) {
        int t = (threadIdx.x >= o) ? sm[threadIdx.x - o] : 0;
        __syncthreads();
        sm[threadIdx.x] += t;
        __syncthreads();
    }
    if (threadIdx.x < nb) g_boff[threadIdx.x] = sm[threadIdx.x] - v;
}

// scan finalize + dinv (fused)
__global__ void scan3(int n, int E) {
    int i = blockIdx.x * blockDim.x + threadIdx.x;
    if (i < n) {
        g_rowptr[i] += g_boff[i >> 9];
        g_dinv[i] = rsqrtf(g_deg[i] + 1.0f);
    }
    if (i == 0) g_rowptr[n] = E;
}

// ---------------- CSR fill (also computes per-edge norm) ----------------
__global__ void fill_kernel(const float* __restrict__ ew, int E) {
    int e = blockIdx.x * blockDim.x + threadIdx.x;
    if (e < E) {
        int s = g_idx[e];
        int d = g_idx[E + e];
        int pos = g_rowptr[d] + atomicAdd(&g_fill[d], 1);
        g_esrc[pos]  = s;
        g_enorm[pos] = g_dinv[s] * ew[e] * g_dinv[d];
    }
}

// ---------------- fused BN+ReLU on load ----------------
__device__ __forceinline__ float4 bnrelu4(float4 v, int c4) {
    float4 sc = ((const float4*)g_scale)[c4];
    float4 sh = ((const float4*)g_shift)[c4];
    v.x = fmaxf(fmaf(v.x, sc.x, sh.x), 0.0f);
    v.y = fmaxf(fmaf(v.y, sc.y, sh.y), 0.0f);
    v.z = fmaxf(fmaf(v.z, sc.z, sh.z), 0.0f);
    v.w = fmaxf(fmaf(v.w, sc.w, sh.w), 0.0f);
    return v;
}

// ---------------- GEMM: xw_h[n,128] = half( act(A[n,128]) @ W[128,128] ) ----------
#define GEMM_SMEM ((128 * 128 + 128 * 132) * 4)

template <bool FUSE_BN>
__global__ void __launch_bounds__(256) gemm128(const float* __restrict__ A,
                                               const float* __restrict__ W,
                                               __half* __restrict__ C, int n) {
    extern __shared__ float smem[];
    float* sW = smem;                 // [128][128]
    float* sX = smem + 128 * 128;     // [128][132] padded

    int tid = threadIdx.x;
    int row0 = blockIdx.x * 128;

    const float4* W4  = (const float4*)W;
    float4*       sW4 = (float4*)sW;
    #pragma unroll
    for (int i = tid; i < 4096; i += 256) sW4[i] = W4[i];

    const float4* A4  = (const float4*)A + (size_t)row0 * 32;
    float4*       sX4 = (float4*)sX;
    #pragma unroll
    for (int i = tid; i < 4096; i += 256) {
        int r = i >> 5, c4 = i & 31;
        float4 v = make_float4(0.f, 0.f, 0.f, 0.f);
        if (row0 + r < n) v = A4[i];
        if (FUSE_BN) v = bnrelu4(v, c4);
        sX4[r * 33 + c4] = v;
    }
    __syncthreads();

    int tx = tid & 15, ty = tid >> 4;
    ull acc[8][4];
    #pragma unroll
    for (int j = 0; j < 8; j++)
        #pragma unroll
        for (int p = 0; p < 4; p++) acc[j][p] = splat2(0.f);

    const ulonglong2* sW2 = (const ulonglong2*)sW;
    #pragma unroll 2
    for (int k = 0; k < 128; k++) {
        ulonglong2 wa = sW2[k * 32 + 2 * tx];
        ulonglong2 wb = sW2[k * 32 + 2 * tx + 1];
        #pragma unroll
        for (int j = 0; j < 8; j++) {
            int row = (j < 4) ? (ty * 4 + j) : (64 + ty * 4 + (j - 4));
            ull xi = splat2(sX[row * 132 + k]);
            acc[j][0] = fma2(xi, wa.x, acc[j][0]);
            acc[j][1] = fma2(xi, wa.y, acc[j][1]);
            acc[j][2] = fma2(xi, wb.x, acc[j][2]);
            acc[j][3] = fma2(xi, wb.y, acc[j][3]);
        }
    }

    #pragma unroll
    for (int j = 0; j < 8; j++) {
        int r = row0 + ((j < 4) ? (ty * 4 + j) : (64 + ty * 4 + (j - 4)));
        if (r < n) {
            uint4 o;
            union { ull u; float2 f; } cv;
            __half2 hh;
            cv.u = acc[j][0]; hh = __floats2half2_rn(cv.f.x, cv.f.y);
            o.x = *reinterpret_cast<unsigned*>(&hh);
            cv.u = acc[j][1]; hh = __floats2half2_rn(cv.f.x, cv.f.y);
            o.y = *reinterpret_cast<unsigned*>(&hh);
            cv.u = acc[j][2]; hh = __floats2half2_rn(cv.f.x, cv.f.y);
            o.z = *reinterpret_cast<unsigned*>(&hh);
            cv.u = acc[j][3]; hh = __floats2half2_rn(cv.f.x, cv.f.y);
            o.w = *reinterpret_cast<unsigned*>(&hh);
            ((uint4*)(C + (size_t)r * D))[tx] = o;
        }
    }
}

// ---------------- GEMM: C[n,40] = half( bnrelu(A[n,128]) @ W[128,40] ) ----------
__global__ void gemm40(const float* __restrict__ A, const float* __restrict__ W,
                       __half* __restrict__ C, int n) {
    __shared__ float sW[128 * 40];
    __shared__ float sX[32 * 132];

    int tid = threadIdx.x;
    int row0 = blockIdx.x * 32;

    const float4* W4  = (const float4*)W;
    float4*       sW4 = (float4*)sW;
    #pragma unroll
    for (int i = tid; i < 1280; i += 256) sW4[i] = W4[i];

    const float4* A4  = (const float4*)A + (size_t)row0 * 32;
    float4*       sX4 = (float4*)sX;
    #pragma unroll
    for (int i = tid; i < 1024; i += 256) {
        int r = i >> 5, c4 = i & 31;
        float4 v = make_float4(0.f, 0.f, 0.f, 0.f);
        if (row0 + r < n) v = A4[i];
        v = bnrelu4(v, c4);
        sX4[r * 33 + c4] = v;
    }
    __syncthreads();

    int tx = tid & 7, rt = tid >> 3;
    float acc[5] = {0.f, 0.f, 0.f, 0.f, 0.f};
    #pragma unroll 4
    for (int k = 0; k < 128; k++) {
        float xv = sX[rt * 132 + k];
        #pragma unroll
        for (int j = 0; j < 5; j++)
            acc[j] = fmaf(xv, sW[k * 40 + tx * 5 + j], acc[j]);
    }
    int row = row0 + rt;
    if (row < n) {
        #pragma unroll
        for (int j = 0; j < 5; j++)
            C[(size_t)row * 40 + tx * 5 + j] = __float2half_rn(acc[j]);
    }
}

// ---------------- CSR gather (fp16 rows) + self-loop + bias + BN stats ----------
__global__ void gather128_bn(const __half* __restrict__ xw, const float* __restrict__ b,
                             float* __restrict__ h, int n) {
    __shared__ float sbs[128], sbss[128];
    int tid = threadIdx.x;
    if (tid < 128) { sbs[tid] = 0.f; sbss[tid] = 0.f; }
    __syncthreads();

    int lane   = tid & 31;
    int warp   = (blockIdx.x * blockDim.x + tid) >> 5;
    int nwarps = (gridDim.x * blockDim.x) >> 5;

    float4 ps  = make_float4(0.f, 0.f, 0.f, 0.f);
    float4 pss = make_float4(0.f, 0.f, 0.f, 0.f);
    float4 bb  = ((const float4*)b)[lane];

    for (int v = warp; v < n; v += nwarps) {
        int beg = g_rowptr[v], end = g_rowptr[v + 1];
        float4 acc = make_float4(0.f, 0.f, 0.f, 0.f);
        for (int i = beg; i < end; i++) {
            int   s = g_esrc[i];
            float w = g_enorm[i];
            uint2 rv = ((const uint2*)(xw + (size_t)s * D))[lane];
            float2 f0 = __half22float2(*reinterpret_cast<__half2*>(&rv.x));
            float2 f1 = __half22float2(*reinterpret_cast<__half2*>(&rv.y));
            acc.x = fmaf(f0.x, w, acc.x);
            acc.y = fmaf(f0.y, w, acc.y);
            acc.z = fmaf(f1.x, w, acc.z);
            acc.w = fmaf(f1.y, w, acc.w);
        }
        float di  = g_dinv[v];
        float di2 = di * di;
        uint2 rv = ((const uint2*)(xw + (size_t)v * D))[lane];
        float2 f0 = __half22float2(*reinterpret_cast<__half2*>(&rv.x));
        float2 f1 = __half22float2(*reinterpret_cast<__half2*>(&rv.y));
        acc.x = fmaf(f0.x, di2, acc.x) + bb.x;
        acc.y = fmaf(f0.y, di2, acc.y) + bb.y;
        acc.z = fmaf(f1.x, di2, acc.z) + bb.z;
        acc.w = fmaf(f1.y, di2, acc.w) + bb.w;
        ((float4*)(h + (size_t)v * D))[lane] = acc;
        ps.x += acc.x; ps.y += acc.y; ps.z += acc.z; ps.w += acc.w;
        pss.x = fmaf(acc.x, acc.x, pss.x);
        pss.y = fmaf(acc.y, acc.y, pss.y);
        pss.z = fmaf(acc.z, acc.z, pss.z);
        pss.w = fmaf(acc.w, acc.w, pss.w);
    }

    atomicAdd(&sbs[lane * 4 + 0], ps.x);
    atomicAdd(&sbs[lane * 4 + 1], ps.y);
    atomicAdd(&sbs[lane * 4 + 2], ps.z);
    atomicAdd(&sbs[lane * 4 + 3], ps.w);
    atomicAdd(&sbss[lane * 4 + 0], pss.x);
    atomicAdd(&sbss[lane * 4 + 1], pss.y);
    atomicAdd(&sbss[lane * 4 + 2], pss.z);
    atomicAdd(&sbss[lane * 4 + 3], pss.w);
    __syncthreads();
    if (tid < 128) {
        atomicAdd(&g_bnsum[tid],   sbs[tid]);
        atomicAdd(&g_bnsumsq[tid], sbss[tid]);
    }
}

__global__ void bn_final(const float* __restrict__ g, const float* __restrict__ be,
                         float fn) {
    int c = threadIdx.x;
    float mean = g_bnsum[c] / fn;
    float var  = g_bnsumsq[c] / fn - mean * mean;
    float sc   = g[c] * rsqrtf(var + 1e-5f);
    g_scale[c] = sc;
    g_shift[c] = be[c] - mean * sc;
}

// ---------------- CSR gather (D=40, fp16) + self-loop + bias + log_softmax --------
__global__ void gather40_softmax(const __half* __restrict__ xw2,
                                 const float* __restrict__ b2, float* __restrict__ out,
                                 int n) {
    int lane   = threadIdx.x & 31;
    int warp   = (blockIdx.x * blockDim.x + threadIdx.x) >> 5;
    int nwarps = (gridDim.x * blockDim.x) >> 5;

    for (int v = warp; v < n; v += nwarps) {
        int beg = g_rowptr[v], end = g_rowptr[v + 1];
        float4 acc = make_float4(0.f, 0.f, 0.f, 0.f);
        if (lane < 10) {
            for (int i = beg; i < end; i++) {
                int   s = g_esrc[i];
                float w = g_enorm[i];
                uint2 rv = ((const uint2*)(xw2 + (size_t)s * DOUT))[lane];
                float2 f0 = __half22float2(*reinterpret_cast<__half2*>(&rv.x));
                float2 f1 = __half22float2(*reinterpret_cast<__half2*>(&rv.y));
                acc.x = fmaf(f0.x, w, acc.x);
                acc.y = fmaf(f0.y, w, acc.y);
                acc.z = fmaf(f1.x, w, acc.z);
                acc.w = fmaf(f1.y, w, acc.w);
            }
            float di  = g_dinv[v];
            float di2 = di * di;
            uint2 rv = ((const uint2*)(xw2 + (size_t)v * DOUT))[lane];
            float2 f0 = __half22float2(*reinterpret_cast<__half2*>(&rv.x));
            float2 f1 = __half22float2(*reinterpret_cast<__half2*>(&rv.y));
            float4 bb = ((const float4*)b2)[lane];
            acc.x = fmaf(f0.x, di2, acc.x) + bb.x;
            acc.y = fmaf(f0.y, di2, acc.y) + bb.y;
            acc.z = fmaf(f1.x, di2, acc.z) + bb.z;
            acc.w = fmaf(f1.y, di2, acc.w) + bb.w;
        }
        float m = (lane < 10)
                ? fmaxf(fmaxf(acc.x, acc.y), fmaxf(acc.z, acc.w)) : -1e30f;
        #pragma unroll
        for (int o = 16; o; o >>= 1) m = fmaxf(m, __shfl_xor_sync(0xffffffffu, m, o));
        float s = (lane < 10)
                ? (expf(acc.x - m) + expf(acc.y - m) + expf(acc.z - m) + expf(acc.w - m))
                : 0.f;
        #pragma unroll
        for (int o = 16; o; o >>= 1) s += __shfl_xor_sync(0xffffffffu, s, o);
        float lse = m + logf(s);
        if (lane < 10)
            ((float4*)(out + (size_t)v * DOUT))[lane] =
                make_float4(acc.x - lse, acc.y - lse, acc.z - lse, acc.w - lse);
    }
}

// ---------------- launch ----------------
extern "C" void kernel_launch(void* const* d_in, const int* in_sizes, int n_in,
                              void* d_out, int out_size) {
    const float* x   = (const float*)d_in[0];
    const void*  ei  = d_in[1];
    const float* ew  = (const float*)d_in[2];
    const float* W0  = (const float*)d_in[3];
    const float* b0  = (const float*)d_in[4];
    const float* g0  = (const float*)d_in[5];
    const float* be0 = (const float*)d_in[6];
    const float* W1  = (const float*)d_in[7];
    const float* b1  = (const float*)d_in[8];
    const float* g1  = (const float*)d_in[9];
    const float* be1 = (const float*)d_in[10];
    const float* W2  = (const float*)d_in[11];
    const float* b2  = (const float*)d_in[12];

    int n = in_sizes[0] / D;
    int E = in_sizes[2];
    int twoE = 2 * E;

    cudaFuncSetAttribute(gemm128<false>, cudaFuncAttributeMaxDynamicSharedMemorySize, GEMM_SMEM);
    cudaFuncSetAttribute(gemm128<true>,  cudaFuncAttributeMaxDynamicSharedMemorySize, GEMM_SMEM);

    void *p_deg, *p_cnt, *p_fill, *p_bns, *p_bnss, *p_xw, *p_h, *p_xw2;
    cudaGetSymbolAddress(&p_deg,  g_deg);
    cudaGetSymbolAddress(&p_cnt,  g_cnt);
    cudaGetSymbolAddress(&p_fill, g_fill);
    cudaGetSymbolAddress(&p_bns,  g_bnsum);
    cudaGetSymbolAddress(&p_bnss, g_bnsumsq);
    cudaGetSymbolAddress(&p_xw,   g_xw);
    cudaGetSymbolAddress(&p_h,    g_h);
    cudaGetSymbolAddress(&p_xw2,  g_xw2);
    __half* xw  = (__half*)p_xw;
    float*  h   = (float*)p_h;
    __half* xw2 = (__half*)p_xw2;

    const int T = 256;
    int nb_scan = cdiv(n, 512);
    int gather_blocks = 1184;

    // fork/join: CSR build (s2) overlapped with layer-0 GEMM (stream 0).
    // kernel_launch runs only a handful of times (correctness + capture), so
    // per-call stream/event creation is fine and keeps every call identical.
    cudaStream_t s2;
    cudaEvent_t evF, evJ;
    cudaStreamCreateWithFlags(&s2, cudaStreamNonBlocking);
    cudaEventCreateWithFlags(&evF, cudaEventDisableTiming);
    cudaEventCreateWithFlags(&evJ, cudaEventDisableTiming);

    cudaEventRecord(evF, 0);
    cudaStreamWaitEvent(s2, evF, 0);

    // ---- branch A (s2): index convert + CSR build ----
    cudaMemsetAsync(p_deg,  0, (size_t)n * sizeof(float), s2);
    cudaMemsetAsync(p_cnt,  0, (size_t)n * sizeof(int), s2);
    cudaMemsetAsync(p_fill, 0, (size_t)n * sizeof(int), s2);
    detect_kernel<<<1, 32, 0, s2>>>((const unsigned*)ei, twoE);
    convert_deg_kernel<<<cdiv(twoE, T), T, 0, s2>>>(ei, ew, E);
    scan1<<<nb_scan, 512, 0, s2>>>(n);
    scan2<<<1, 256, 0, s2>>>(nb_scan);
    scan3<<<cdiv(n, T), T, 0, s2>>>(n, E);
    fill_kernel<<<cdiv(E, T), T, 0, s2>>>(ew, E);
    cudaEventRecord(evJ, s2);

    // ---- branch B (stream 0): layer-0 GEMM ----
    gemm128<false><<<cdiv(n, 128), T, GEMM_SMEM>>>(x, W0, xw, n);
    cudaMemsetAsync(p_bns, 0, D * sizeof(float), 0);
    cudaMemsetAsync(p_bnss, 0, D * sizeof(float), 0);

    // join
    cudaStreamWaitEvent(0, evJ, 0);

    // ---- layer 0 aggregate ----
    gather128_bn<<<gather_blocks, T>>>(xw, b0, h, n);
    bn_final<<<1, D>>>(g0, be0, (float)n);

    // ---- layer 1 ----
    gemm128<true><<<cdiv(n, 128), T, GEMM_SMEM>>>(h, W1, xw, n);
    cudaMemsetAsync(p_bns, 0, D * sizeof(float), 0);
    cudaMemsetAsync(p_bnss, 0, D * sizeof(float), 0);
    gather128_bn<<<gather_blocks, T>>>(xw, b1, h, n);
    bn_final<<<1, D>>>(g1, be1, (float)n);

    // ---- layer 2 + log_softmax ----
    gemm40<<<cdiv(n, 32), T>>>(h, W2, xw2, n);
    gather40_softmax<<<gather_blocks, T>>>(xw2, b2, (float*)d_out, n);

    cudaEventDestroy(evF);
    cudaEventDestroy(evJ);
    cudaStreamDestroy(s2);
}